// round 10
// baseline (speedup 1.0000x reference)
#include <cuda_runtime.h>
#include <cuda_bf16.h>
#include <cstdint>

#define N_NODES 100000
#define DIM 128
#define N_INC 1600000
#define ELL_PAD 64           // Poisson(16) degrees: P(deg>=64) ~ 1e-18 per segment

// Scratch (static device globals: allocation-free per harness rules)
__device__ __nv_bfloat16 g_h[(size_t)N_NODES * DIM];
__device__ __nv_bfloat16 g_e[(size_t)N_NODES * DIM];
__device__ __nv_bfloat16 g_o[(size_t)N_NODES * DIM];
__device__ float g_dinv[N_NODES];
__device__ float g_binv[N_NODES];
__device__ float g_acc[DIM];
__device__ int   g_cnt_n[N_NODES];
__device__ int   g_cnt_h[N_NODES];
__device__ int   g_ell_n[(size_t)N_NODES * ELL_PAD];   // hedges incident to node
__device__ int   g_ell_h[(size_t)N_NODES * ELL_PAD];   // nodes in hedge

// --------------------------- setup kernels ---------------------------------

__global__ void init_kernel(int* __restrict__ cn, int* __restrict__ ch,
                            float* __restrict__ acc, int n) {
    int i = blockIdx.x * blockDim.x + threadIdx.x;
    if (i < n) { cn[i] = 0; ch[i] = 0; }
    if (i < DIM) acc[i] = 0.0f;
}

__global__ void fill_ell_kernel(const int* __restrict__ nidx, const int* __restrict__ hidx,
                                int* __restrict__ cnt_n, int* __restrict__ cnt_h,
                                int* __restrict__ ell_n, int* __restrict__ ell_h, int n) {
    int i = blockIdx.x * blockDim.x + threadIdx.x;
    if (i < n) {
        int nd = __ldg(nidx + i), hd = __ldg(hidx + i);
        int r1 = atomicAdd(cnt_h + hd, 1);
        if (r1 < ELL_PAD) ell_h[(size_t)hd * ELL_PAD + r1] = nd;
        int r2 = atomicAdd(cnt_n + nd, 1);
        if (r2 < ELL_PAD) ell_n[(size_t)nd * ELL_PAD + r2] = hd;
    }
}

__global__ void invert_from_counts(const int* __restrict__ cn, const int* __restrict__ ch,
                                   float* __restrict__ dinv, float* __restrict__ binv, int n) {
    int i = blockIdx.x * blockDim.x + threadIdx.x;
    if (i < n) {
        int a = cn[i]; dinv[i] = (a > 0) ? 1.0f / (float)a : 0.0f;
        int b = ch[i]; binv[i] = (b > 0) ? 1.0f / (float)b : 0.0f;
    }
}

// ------------------------- bf16 gather segment sums (ELL) -------------------

struct Acc8 { float v[8]; };

__device__ __forceinline__ void bf16_row_add16(Acc8& a, const __nv_bfloat16* __restrict__ src,
                                               int s, int lane16) {
    uint4 r = __ldg((const uint4*)(src + (size_t)s * DIM) + lane16);
    const __nv_bfloat162* p = reinterpret_cast<const __nv_bfloat162*>(&r);
    #pragma unroll
    for (int i = 0; i < 4; i++) {
        float2 f = __bfloat1622float2(p[i]);
        a.v[2 * i]     += f.x;
        a.v[2 * i + 1] += f.y;
    }
}

template <bool FUSE_SCALE>
__global__ void gather_kernel(const __nv_bfloat16* __restrict__ src, const int* __restrict__ cnt,
                              const int* __restrict__ ell, const float* __restrict__ scale,
                              __nv_bfloat16* __restrict__ dst, int n) {
    int d = (blockIdx.x * blockDim.x + threadIdx.x) >> 4;
    if (d >= n) return;
    int lane = threadIdx.x & 15;
    int deg = __ldg(cnt + d);
    if (deg > ELL_PAD) deg = ELL_PAD;
    const int* adj = ell + (size_t)d * ELL_PAD;
    Acc8 acc;
    #pragma unroll
    for (int i = 0; i < 8; i++) acc.v[i] = 0.0f;
    int p = 0;
    for (; p + 3 < deg; p += 4) {
        int4 s4 = __ldg((const int4*)(adj + p));
        bf16_row_add16(acc, src, s4.x, lane);
        bf16_row_add16(acc, src, s4.y, lane);
        bf16_row_add16(acc, src, s4.z, lane);
        bf16_row_add16(acc, src, s4.w, lane);
    }
    for (; p < deg; p++) bf16_row_add16(acc, src, __ldg(adj + p), lane);
    if (FUSE_SCALE) {
        float sc = __ldg(scale + d);
        #pragma unroll
        for (int i = 0; i < 8; i++) acc.v[i] *= sc;
    }
    uint4 w;
    __nv_bfloat162* wp = reinterpret_cast<__nv_bfloat162*>(&w);
    #pragma unroll
    for (int i = 0; i < 4; i++)
        wp[i] = __float22bfloat162_rn(make_float2(acc.v[2 * i], acc.v[2 * i + 1]));
    *((uint4*)(dst + (size_t)d * DIM) + lane) = w;
}

// Final pass: node-gather + relu(acc*dinv + b2) + column-mean accumulation.
__global__ void gather_mean_kernel(const __nv_bfloat16* __restrict__ src, const int* __restrict__ cnt,
                                   const int* __restrict__ ell, const float* __restrict__ dinv,
                                   const float* __restrict__ bias, float* __restrict__ acc_out,
                                   int n) {
    __shared__ float blk[DIM];
    int t = threadIdx.x;
    if (t < DIM) blk[t] = 0.0f;
    __syncthreads();
    int d = (blockIdx.x * blockDim.x + t) >> 4;
    int lane = t & 15;
    if (d < n) {
        int deg = __ldg(cnt + d);
        if (deg > ELL_PAD) deg = ELL_PAD;
        const int* adj = ell + (size_t)d * ELL_PAD;
        Acc8 acc;
        #pragma unroll
        for (int i = 0; i < 8; i++) acc.v[i] = 0.0f;
        int p = 0;
        for (; p + 3 < deg; p += 4) {
            int4 s4 = __ldg((const int4*)(adj + p));
            bf16_row_add16(acc, src, s4.x, lane);
            bf16_row_add16(acc, src, s4.y, lane);
            bf16_row_add16(acc, src, s4.z, lane);
            bf16_row_add16(acc, src, s4.w, lane);
        }
        for (; p < deg; p++) bf16_row_add16(acc, src, __ldg(adj + p), lane);
        float di = __ldg(dinv + d);
        float4 b0 = __ldg((const float4*)bias + lane * 2);
        float4 b1 = __ldg((const float4*)bias + lane * 2 + 1);
        float bb[8] = {b0.x, b0.y, b0.z, b0.w, b1.x, b1.y, b1.z, b1.w};
        #pragma unroll
        for (int i = 0; i < 8; i++) {
            float r = fmaxf(fmaf(acc.v[i], di, bb[i]), 0.0f);
            atomicAdd(blk + lane * 8 + i, r);
        }
    }
    __syncthreads();
    if (t < DIM) atomicAdd(acc_out + t, blk[t]);
}

__global__ void finalize_kernel(const float* __restrict__ acc, float* __restrict__ out) {
    int c = threadIdx.x;
    out[c] = acc[c] * (1.0f / N_NODES);
}

// ------------------------- tf32 tensor-core GEMM ---------------------------
// C_bf16[M,128] = A'[M,128] @ W[128,128], tf32 MMA (m16n8k8), fp32 accumulate.
// Block tile 128 rows x 64 cols (grid = 2 * row-blocks): Bp holds only half
// of W (32KB) -> smem 69.6KB -> 3 CTAs/SM. Warp tile 32x32 (4x2 warp grid).
// Numerics identical to the round-6/9 passing versions.

__device__ __forceinline__ uint32_t f2tf(float f) {
    uint32_t r;
    asm("cvt.rna.tf32.f32 %0, %1;" : "=r"(r) : "f"(f));
    return r;
}

#define BPH_STRIDE 68   // uint2 per (s,tig) row: 64 + 4 pad  (68 mod 16 == 4)
#define AS_STRIDE 68    // uint32 per A row: 64 + 4 pad

template <bool PREACT, bool A_BF16>
__global__ __launch_bounds__(256) void gemm_tc_kernel(
        const void* __restrict__ A_raw, const float* __restrict__ W,
        const float* __restrict__ dinv, const float* __restrict__ bias,
        __nv_bfloat16* __restrict__ C, int M) {
    extern __shared__ char smem_raw[];
    uint2* Bp = (uint2*)smem_raw;                               // 64*68*8 = 34816 B
    uint32_t* As = (uint32_t*)(smem_raw + 64 * BPH_STRIDE * 8); // 128*68*4 = 34816 B

    const int tid = threadIdx.x;
    const int rb = blockIdx.x >> 1;         // row block
    const int nb = blockIdx.x & 1;          // n half (0: cols 0-63, 1: 64-127)
    const int m0 = rb * 128;
    const int n_base = nb * 64;
    const int warp = tid >> 5;
    const int lane = tid & 31;
    const int grp = lane >> 2;     // 0..7
    const int tig = lane & 3;      // 0..3
    const int rw = warp >> 1;      // row group 0..3 -> rows [rw*32, rw*32+32)
    const int cw = warp & 1;       // col group 0..1 -> n-tiles [cw*4, cw*4+4) (of 8)
    const int r0 = rw * 32;

    // ---- Pack this block's half of W into tf32 fragment layout ----
    // uint2 at [(s*4+tg)*BPH_STRIDE + t*8 + g] =
    //   {W[8s+tg][n_base+8t+g], W[8s+tg+4][n_base+8t+g]},  t in 0..7.
    for (int idx = tid; idx < 4096; idx += 256) {
        int g = idx & 7;
        int t = (idx >> 3) & 7;
        int tg = (idx >> 6) & 3;
        int s = idx >> 8;
        int k0 = 8 * s + tg;
        int n = n_base + 8 * t + g;
        uint2 v;
        v.x = f2tf(__ldg(W + k0 * DIM + n));
        v.y = f2tf(__ldg(W + (k0 + 4) * DIM + n));
        Bp[(s * 4 + tg) * BPH_STRIDE + t * 8 + g] = v;
    }

    float c[2][4][4];   // [m-tile][n-tile][reg]
    #pragma unroll
    for (int mt = 0; mt < 2; mt++)
        #pragma unroll
        for (int t = 0; t < 4; t++)
            #pragma unroll
            for (int j = 0; j < 4; j++) c[mt][t][j] = 0.0f;

    for (int kc = 0; kc < 2; kc++) {
        __syncthreads();
        // ---- Stage A chunk (pre-converted to tf32 bits): rows 0..127, k 64 ----
        #pragma unroll
        for (int i = tid; i < 2048; i += 256) {
            int row = i >> 4;
            int kq = (i & 15) << 2;
            int m = m0 + row;
            float4 v = make_float4(0.f, 0.f, 0.f, 0.f);
            if (m < M) {
                if (A_BF16) {
                    const __nv_bfloat16* Ab = (const __nv_bfloat16*)A_raw;
                    uint2 raw = __ldg((const uint2*)(Ab + (size_t)m * DIM + kc * 64 + kq));
                    __nv_bfloat162 p0 = *reinterpret_cast<const __nv_bfloat162*>(&raw.x);
                    __nv_bfloat162 p1 = *reinterpret_cast<const __nv_bfloat162*>(&raw.y);
                    float2 f0 = __bfloat1622float2(p0);
                    float2 f1 = __bfloat1622float2(p1);
                    v = make_float4(f0.x, f0.y, f1.x, f1.y);
                } else {
                    const float* Af = (const float*)A_raw;
                    v = __ldg((const float4*)(Af + (size_t)m * DIM + kc * 64 + kq));
                }
                if (PREACT) {
                    float di = __ldg(dinv + m);
                    const float* bp = bias + kc * 64 + kq;
                    v.x = fmaxf(fmaf(v.x, di, __ldg(bp + 0)), 0.0f);
                    v.y = fmaxf(fmaf(v.y, di, __ldg(bp + 1)), 0.0f);
                    v.z = fmaxf(fmaf(v.z, di, __ldg(bp + 2)), 0.0f);
                    v.w = fmaxf(fmaf(v.w, di, __ldg(bp + 3)), 0.0f);
                }
            }
            uint4 tv = make_uint4(f2tf(v.x), f2tf(v.y), f2tf(v.z), f2tf(v.w));
            *(uint4*)(As + row * AS_STRIDE + kq) = tv;
        }
        __syncthreads();

        // ---- 8 k-steps: load A frags for both m-tiles, sweep 4 n-tiles ----
        #pragma unroll
        for (int sl = 0; sl < 8; sl++) {
            int kk = 8 * sl + tig;
            uint32_t a0[4], a1[4];
            a0[0] = As[(r0 + grp) * AS_STRIDE + kk];
            a0[1] = As[(r0 + grp + 8) * AS_STRIDE + kk];
            a0[2] = As[(r0 + grp) * AS_STRIDE + kk + 4];
            a0[3] = As[(r0 + grp + 8) * AS_STRIDE + kk + 4];
            a1[0] = As[(r0 + 16 + grp) * AS_STRIDE + kk];
            a1[1] = As[(r0 + 16 + grp + 8) * AS_STRIDE + kk];
            a1[2] = As[(r0 + 16 + grp) * AS_STRIDE + kk + 4];
            a1[3] = As[(r0 + 16 + grp + 8) * AS_STRIDE + kk + 4];
            int s = kc * 8 + sl;
            #pragma unroll
            for (int t4 = 0; t4 < 4; t4++) {
                int t = cw * 4 + t4;
                uint2 b = Bp[(s * 4 + tig) * BPH_STRIDE + t * 8 + grp];
                asm volatile(
                    "mma.sync.aligned.m16n8k8.row.col.f32.tf32.tf32.f32 "
                    "{%0,%1,%2,%3}, {%4,%5,%6,%7}, {%8,%9}, {%0,%1,%2,%3};"
                    : "+f"(c[0][t4][0]), "+f"(c[0][t4][1]), "+f"(c[0][t4][2]), "+f"(c[0][t4][3])
                    : "r"(a0[0]), "r"(a0[1]), "r"(a0[2]), "r"(a0[3]),
                      "r"(b.x), "r"(b.y));
                asm volatile(
                    "mma.sync.aligned.m16n8k8.row.col.f32.tf32.tf32.f32 "
                    "{%0,%1,%2,%3}, {%4,%5,%6,%7}, {%8,%9}, {%0,%1,%2,%3};"
                    : "+f"(c[1][t4][0]), "+f"(c[1][t4][1]), "+f"(c[1][t4][2]), "+f"(c[1][t4][3])
                    : "r"(a1[0]), "r"(a1[1]), "r"(a1[2]), "r"(a1[3]),
                      "r"(b.x), "r"(b.y));
            }
        }
    }

    // ---- Epilogue: warp covers rows [m0+r0, +32), cols n_base + [cw*32, +32) ----
    #pragma unroll
    for (int mt = 0; mt < 2; mt++) {
        int mlo = m0 + r0 + mt * 16 + grp;
        int mhi = mlo + 8;
        #pragma unroll
        for (int t4 = 0; t4 < 4; t4++) {
            int n = n_base + cw * 32 + 8 * t4 + 2 * tig;
            if (mlo < M) {
                __nv_bfloat162 p = __float22bfloat162_rn(make_float2(c[mt][t4][0], c[mt][t4][1]));
                *(__nv_bfloat162*)(C + (size_t)mlo * DIM + n) = p;
            }
            if (mhi < M) {
                __nv_bfloat162 p = __float22bfloat162_rn(make_float2(c[mt][t4][2], c[mt][t4][3]));
                *(__nv_bfloat162*)(C + (size_t)mhi * DIM + n) = p;
            }
        }
    }
}

// ------------------------------- launch ------------------------------------

extern "C" void kernel_launch(void* const* d_in, const int* in_sizes, int n_in,
                              void* d_out, int out_size) {
    const float* x   = (const float*)d_in[0];
    const int*   ei  = (const int*)d_in[1];
    const int*   nidx = ei;
    const int*   hidx = ei + N_INC;
    const float* w1  = (const float*)d_in[2];
    const float* b1  = (const float*)d_in[3];
    const float* w2  = (const float*)d_in[4];
    const float* b2  = (const float*)d_in[5];
    float* out = (float*)d_out;

    __nv_bfloat16 *h, *e, *o;
    float *dinv, *binv, *acc;
    int *cnt_n, *cnt_h, *ell_n, *ell_h;
    cudaGetSymbolAddress((void**)&h,     g_h);
    cudaGetSymbolAddress((void**)&e,     g_e);
    cudaGetSymbolAddress((void**)&o,     g_o);
    cudaGetSymbolAddress((void**)&dinv,  g_dinv);
    cudaGetSymbolAddress((void**)&binv,  g_binv);
    cudaGetSymbolAddress((void**)&acc,   g_acc);
    cudaGetSymbolAddress((void**)&cnt_n, g_cnt_n);
    cudaGetSymbolAddress((void**)&cnt_h, g_cnt_h);
    cudaGetSymbolAddress((void**)&ell_n, g_ell_n);
    cudaGetSymbolAddress((void**)&ell_h, g_ell_h);

    const int gemm_smem = 64 * BPH_STRIDE * 8 + 128 * AS_STRIDE * 4;  // 69632 B
    cudaFuncSetAttribute((const void*)gemm_tc_kernel<false, false>,
                         cudaFuncAttributeMaxDynamicSharedMemorySize, gemm_smem);
    cudaFuncSetAttribute((const void*)gemm_tc_kernel<true, true>,
                         cudaFuncAttributeMaxDynamicSharedMemorySize, gemm_smem);

    const int TB = 256;
    const int zb_nodes = (N_NODES + TB - 1) / TB;
    const int db_inc   = (N_INC + TB - 1) / TB;
    const int gemm_grid = 2 * ((N_NODES + 127) / 128);
    const int gather_grid = (int)(((long long)N_NODES * 16 + TB - 1) / TB);

    init_kernel<<<zb_nodes, TB>>>(cnt_n, cnt_h, acc, N_NODES);
    fill_ell_kernel<<<db_inc, TB>>>(nidx, hidx, cnt_n, cnt_h, ell_n, ell_h, N_INC);
    invert_from_counts<<<zb_nodes, TB>>>(cnt_n, cnt_h, dinv, binv, N_NODES);

    // ---- Layer 1 ----
    gemm_tc_kernel<false, false><<<gemm_grid, TB, gemm_smem>>>(x, w1, nullptr, nullptr, h, N_NODES);
    gather_kernel<true><<<gather_grid, TB>>>(h, cnt_h, ell_h, binv, e, N_NODES);     // e = Binv H^T h
    gather_kernel<false><<<gather_grid, TB>>>(e, cnt_n, ell_n, nullptr, o, N_NODES); // o = H e

    // ---- Layer 2 (layer-1 dinv/bias/relu fused into GEMM A-staging) ----
    gemm_tc_kernel<true, true><<<gemm_grid, TB, gemm_smem>>>(o, w2, dinv, b1, h, N_NODES);
    gather_kernel<true><<<gather_grid, TB>>>(h, cnt_h, ell_h, binv, e, N_NODES);     // e2 = Binv H^T h

    // ---- Final: fused node-gather + relu(.*dinv + b2) + column mean ----
    gather_mean_kernel<<<gather_grid, TB>>>(e, cnt_n, ell_n, dinv, b2, acc, N_NODES);
    finalize_kernel<<<1, DIM>>>(acc, out);
}

// round 11
// speedup vs baseline: 1.1850x; 1.1850x over previous
#include <cuda_runtime.h>
#include <cuda_bf16.h>
#include <cstdint>

#define N_NODES 100000
#define DIM 128
#define N_INC 1600000
#define ELL_PAD 64           // Poisson(16) degrees: P(deg>=64) ~ 1e-18 per segment

// Scratch (static device globals: allocation-free per harness rules)
__device__ __nv_bfloat16 g_h[(size_t)N_NODES * DIM];
__device__ __nv_bfloat16 g_e[(size_t)N_NODES * DIM];
__device__ __nv_bfloat16 g_o[(size_t)N_NODES * DIM];
__device__ float g_dinv[N_NODES];
__device__ float g_binv[N_NODES];
__device__ float g_acc[DIM];
__device__ int   g_cnt_n[N_NODES];
__device__ int   g_cnt_h[N_NODES];
__device__ int   g_ell_n[(size_t)N_NODES * ELL_PAD];   // hedges incident to node
__device__ int   g_ell_h[(size_t)N_NODES * ELL_PAD];   // nodes in hedge
__device__ uint2 g_w1p[8192];   // W1 pre-packed tf32 fragments (64 KB)
__device__ uint2 g_w2p[8192];   // W2 pre-packed tf32 fragments (64 KB)

// --------------------------- setup kernels ---------------------------------

__global__ void init_kernel(int* __restrict__ cn, int* __restrict__ ch,
                            float* __restrict__ acc, int n) {
    int i = blockIdx.x * blockDim.x + threadIdx.x;
    if (i < n) { cn[i] = 0; ch[i] = 0; }
    if (i < DIM) acc[i] = 0.0f;
}

__global__ void fill_ell_kernel(const int* __restrict__ nidx, const int* __restrict__ hidx,
                                int* __restrict__ cnt_n, int* __restrict__ cnt_h,
                                int* __restrict__ ell_n, int* __restrict__ ell_h, int n) {
    int i = blockIdx.x * blockDim.x + threadIdx.x;
    if (i < n) {
        int nd = __ldg(nidx + i), hd = __ldg(hidx + i);
        int r1 = atomicAdd(cnt_h + hd, 1);
        if (r1 < ELL_PAD) ell_h[(size_t)hd * ELL_PAD + r1] = nd;
        int r2 = atomicAdd(cnt_n + nd, 1);
        if (r2 < ELL_PAD) ell_n[(size_t)nd * ELL_PAD + r2] = hd;
    }
}

__global__ void invert_from_counts(const int* __restrict__ cn, const int* __restrict__ ch,
                                   float* __restrict__ dinv, float* __restrict__ binv, int n) {
    int i = blockIdx.x * blockDim.x + threadIdx.x;
    if (i < n) {
        int a = cn[i]; dinv[i] = (a > 0) ? 1.0f / (float)a : 0.0f;
        int b = ch[i]; binv[i] = (b > 0) ? 1.0f / (float)b : 0.0f;
    }
}

// ------------------------- bf16 gather segment sums (ELL) -------------------

struct Acc8 { float v[8]; };

__device__ __forceinline__ void bf16_row_add16(Acc8& a, const __nv_bfloat16* __restrict__ src,
                                               int s, int lane16) {
    uint4 r = __ldg((const uint4*)(src + (size_t)s * DIM) + lane16);
    const __nv_bfloat162* p = reinterpret_cast<const __nv_bfloat162*>(&r);
    #pragma unroll
    for (int i = 0; i < 4; i++) {
        float2 f = __bfloat1622float2(p[i]);
        a.v[2 * i]     += f.x;
        a.v[2 * i + 1] += f.y;
    }
}

template <bool FUSE_SCALE>
__global__ void gather_kernel(const __nv_bfloat16* __restrict__ src, const int* __restrict__ cnt,
                              const int* __restrict__ ell, const float* __restrict__ scale,
                              __nv_bfloat16* __restrict__ dst, int n) {
    int d = (blockIdx.x * blockDim.x + threadIdx.x) >> 4;
    if (d >= n) return;
    int lane = threadIdx.x & 15;
    int deg = __ldg(cnt + d);
    if (deg > ELL_PAD) deg = ELL_PAD;
    const int* adj = ell + (size_t)d * ELL_PAD;
    Acc8 acc;
    #pragma unroll
    for (int i = 0; i < 8; i++) acc.v[i] = 0.0f;
    int p = 0;
    for (; p + 3 < deg; p += 4) {
        int4 s4 = __ldg((const int4*)(adj + p));
        bf16_row_add16(acc, src, s4.x, lane);
        bf16_row_add16(acc, src, s4.y, lane);
        bf16_row_add16(acc, src, s4.z, lane);
        bf16_row_add16(acc, src, s4.w, lane);
    }
    for (; p < deg; p++) bf16_row_add16(acc, src, __ldg(adj + p), lane);
    if (FUSE_SCALE) {
        float sc = __ldg(scale + d);
        #pragma unroll
        for (int i = 0; i < 8; i++) acc.v[i] *= sc;
    }
    uint4 w;
    __nv_bfloat162* wp = reinterpret_cast<__nv_bfloat162*>(&w);
    #pragma unroll
    for (int i = 0; i < 4; i++)
        wp[i] = __float22bfloat162_rn(make_float2(acc.v[2 * i], acc.v[2 * i + 1]));
    *((uint4*)(dst + (size_t)d * DIM) + lane) = w;
}

// Final pass: node-gather + relu(acc*dinv + b2) + column-mean accumulation.
__global__ void gather_mean_kernel(const __nv_bfloat16* __restrict__ src, const int* __restrict__ cnt,
                                   const int* __restrict__ ell, const float* __restrict__ dinv,
                                   const float* __restrict__ bias, float* __restrict__ acc_out,
                                   int n) {
    __shared__ float blk[DIM];
    int t = threadIdx.x;
    if (t < DIM) blk[t] = 0.0f;
    __syncthreads();
    int d = (blockIdx.x * blockDim.x + t) >> 4;
    int lane = t & 15;
    if (d < n) {
        int deg = __ldg(cnt + d);
        if (deg > ELL_PAD) deg = ELL_PAD;
        const int* adj = ell + (size_t)d * ELL_PAD;
        Acc8 acc;
        #pragma unroll
        for (int i = 0; i < 8; i++) acc.v[i] = 0.0f;
        int p = 0;
        for (; p + 3 < deg; p += 4) {
            int4 s4 = __ldg((const int4*)(adj + p));
            bf16_row_add16(acc, src, s4.x, lane);
            bf16_row_add16(acc, src, s4.y, lane);
            bf16_row_add16(acc, src, s4.z, lane);
            bf16_row_add16(acc, src, s4.w, lane);
        }
        for (; p < deg; p++) bf16_row_add16(acc, src, __ldg(adj + p), lane);
        float di = __ldg(dinv + d);
        float4 b0 = __ldg((const float4*)bias + lane * 2);
        float4 b1 = __ldg((const float4*)bias + lane * 2 + 1);
        float bb[8] = {b0.x, b0.y, b0.z, b0.w, b1.x, b1.y, b1.z, b1.w};
        #pragma unroll
        for (int i = 0; i < 8; i++) {
            float r = fmaxf(fmaf(acc.v[i], di, bb[i]), 0.0f);
            atomicAdd(blk + lane * 8 + i, r);
        }
    }
    __syncthreads();
    if (t < DIM) atomicAdd(acc_out + t, blk[t]);
}

__global__ void finalize_kernel(const float* __restrict__ acc, float* __restrict__ out) {
    int c = threadIdx.x;
    out[c] = acc[c] * (1.0f / N_NODES);
}

// ------------------------- tf32 tensor-core GEMM ---------------------------
// C_bf16[M,128] = A'[M,128] @ W[128,128], tf32 MMA (m16n8k8), fp32 accumulate.
// Round-9 shape (block 128x128, warp tile 32x64) but W fragments are packed
// ONCE by pack_w_kernel; GEMM blocks do a coalesced uint4 gmem->smem copy.

__device__ __forceinline__ uint32_t f2tf(float f) {
    uint32_t r;
    asm("cvt.rna.tf32.f32 %0, %1;" : "=r"(r) : "f"(f));
    return r;
}

#define BP_STRIDE 132   // uint2 per (s,tig) row: 128 + 4 pad
#define AS_STRIDE 68    // uint32 per A row: 64 + 4 pad

// One-time pack of both weight matrices into tf32 fragment layout.
// Layout (linear, no pad): wp[(s*4+tg)*128 + t*8 + g] =
//   {tf32(W[8s+tg][8t+g]), tf32(W[8s+tg+4][8t+g])}
__global__ void pack_w_kernel(const float* __restrict__ W1, const float* __restrict__ W2,
                              uint2* __restrict__ w1p, uint2* __restrict__ w2p) {
    int idx = blockIdx.x * blockDim.x + threadIdx.x;   // 0..8191
    if (idx >= 8192) return;
    int g = idx & 7;
    int t = (idx >> 3) & 15;
    int tg = (idx >> 7) & 3;
    int s = idx >> 9;
    int k0 = 8 * s + tg;
    int n = 8 * t + g;
    uint2 v1, v2;
    v1.x = f2tf(__ldg(W1 + k0 * DIM + n));
    v1.y = f2tf(__ldg(W1 + (k0 + 4) * DIM + n));
    v2.x = f2tf(__ldg(W2 + k0 * DIM + n));
    v2.y = f2tf(__ldg(W2 + (k0 + 4) * DIM + n));
    int dst = (s * 4 + tg) * 128 + t * 8 + g;
    w1p[dst] = v1;
    w2p[dst] = v2;
}

template <bool PREACT, bool A_BF16>
__global__ __launch_bounds__(256) void gemm_tc_kernel(
        const void* __restrict__ A_raw, const uint2* __restrict__ Wp,
        const float* __restrict__ dinv, const float* __restrict__ bias,
        __nv_bfloat16* __restrict__ C, int M) {
    extern __shared__ char smem_raw[];
    uint2* Bp = (uint2*)smem_raw;                               // 64*132*8 = 67584 B
    uint32_t* As = (uint32_t*)(smem_raw + 64 * BP_STRIDE * 8);  // 128*68*4 = 34816 B

    const int tid = threadIdx.x;
    const int m0 = blockIdx.x * 128;
    const int warp = tid >> 5;
    const int lane = tid & 31;
    const int grp = lane >> 2;     // 0..7
    const int tig = lane & 3;      // 0..3
    const int rw = warp >> 1;      // row group 0..3 -> rows [rw*32, rw*32+32)
    const int cw = warp & 1;       // col group 0..1 -> n-tiles [cw*8, cw*8+8)
    const int r0 = rw * 32;

    // ---- Coalesced copy of pre-packed W fragments into padded smem ----
    // 8192 uint2 = 4096 uint4; row = 64 uint4 wide; BP_STRIDE(132)*8B is
    // 16B-aligned per row (1056 % 16 == 0).
    {
        const uint4* src = (const uint4*)Wp;
        #pragma unroll
        for (int i = tid; i < 4096; i += 256) {
            int row = i >> 6;          // 0..63
            int c4  = i & 63;          // uint4 column
            uint4 v = __ldg(src + i);
            *(uint4*)(Bp + row * BP_STRIDE + 2 * c4) = v;
        }
    }

    float c[2][8][4];   // [m-tile][n-tile][reg]
    #pragma unroll
    for (int mt = 0; mt < 2; mt++)
        #pragma unroll
        for (int t = 0; t < 8; t++)
            #pragma unroll
            for (int j = 0; j < 4; j++) c[mt][t][j] = 0.0f;

    for (int kc = 0; kc < 2; kc++) {
        __syncthreads();
        // ---- Stage A chunk (pre-converted to tf32 bits): rows 0..127, k 64 ----
        #pragma unroll
        for (int i = tid; i < 2048; i += 256) {
            int row = i >> 4;
            int kq = (i & 15) << 2;
            int m = m0 + row;
            float4 v = make_float4(0.f, 0.f, 0.f, 0.f);
            if (m < M) {
                if (A_BF16) {
                    const __nv_bfloat16* Ab = (const __nv_bfloat16*)A_raw;
                    uint2 raw = __ldg((const uint2*)(Ab + (size_t)m * DIM + kc * 64 + kq));
                    __nv_bfloat162 p0 = *reinterpret_cast<const __nv_bfloat162*>(&raw.x);
                    __nv_bfloat162 p1 = *reinterpret_cast<const __nv_bfloat162*>(&raw.y);
                    float2 f0 = __bfloat1622float2(p0);
                    float2 f1 = __bfloat1622float2(p1);
                    v = make_float4(f0.x, f0.y, f1.x, f1.y);
                } else {
                    const float* Af = (const float*)A_raw;
                    v = __ldg((const float4*)(Af + (size_t)m * DIM + kc * 64 + kq));
                }
                if (PREACT) {
                    float di = __ldg(dinv + m);
                    const float* bp = bias + kc * 64 + kq;
                    v.x = fmaxf(fmaf(v.x, di, __ldg(bp + 0)), 0.0f);
                    v.y = fmaxf(fmaf(v.y, di, __ldg(bp + 1)), 0.0f);
                    v.z = fmaxf(fmaf(v.z, di, __ldg(bp + 2)), 0.0f);
                    v.w = fmaxf(fmaf(v.w, di, __ldg(bp + 3)), 0.0f);
                }
            }
            uint4 tv = make_uint4(f2tf(v.x), f2tf(v.y), f2tf(v.z), f2tf(v.w));
            *(uint4*)(As + row * AS_STRIDE + kq) = tv;
        }
        __syncthreads();

        // ---- 8 k-steps: load A frags for both m-tiles, sweep 8 n-tiles ----
        #pragma unroll
        for (int sl = 0; sl < 8; sl++) {
            int kk = 8 * sl + tig;
            uint32_t a0[4], a1[4];
            a0[0] = As[(r0 + grp) * AS_STRIDE + kk];
            a0[1] = As[(r0 + grp + 8) * AS_STRIDE + kk];
            a0[2] = As[(r0 + grp) * AS_STRIDE + kk + 4];
            a0[3] = As[(r0 + grp + 8) * AS_STRIDE + kk + 4];
            a1[0] = As[(r0 + 16 + grp) * AS_STRIDE + kk];
            a1[1] = As[(r0 + 16 + grp + 8) * AS_STRIDE + kk];
            a1[2] = As[(r0 + 16 + grp) * AS_STRIDE + kk + 4];
            a1[3] = As[(r0 + 16 + grp + 8) * AS_STRIDE + kk + 4];
            int s = kc * 8 + sl;
            #pragma unroll
            for (int t8 = 0; t8 < 8; t8++) {
                int t = cw * 8 + t8;
                uint2 b = Bp[(s * 4 + tig) * BP_STRIDE + t * 8 + grp];
                asm volatile(
                    "mma.sync.aligned.m16n8k8.row.col.f32.tf32.tf32.f32 "
                    "{%0,%1,%2,%3}, {%4,%5,%6,%7}, {%8,%9}, {%0,%1,%2,%3};"
                    : "+f"(c[0][t8][0]), "+f"(c[0][t8][1]), "+f"(c[0][t8][2]), "+f"(c[0][t8][3])
                    : "r"(a0[0]), "r"(a0[1]), "r"(a0[2]), "r"(a0[3]),
                      "r"(b.x), "r"(b.y));
                asm volatile(
                    "mma.sync.aligned.m16n8k8.row.col.f32.tf32.tf32.f32 "
                    "{%0,%1,%2,%3}, {%4,%5,%6,%7}, {%8,%9}, {%0,%1,%2,%3};"
                    : "+f"(c[1][t8][0]), "+f"(c[1][t8][1]), "+f"(c[1][t8][2]), "+f"(c[1][t8][3])
                    : "r"(a1[0]), "r"(a1[1]), "r"(a1[2]), "r"(a1[3]),
                      "r"(b.x), "r"(b.y));
            }
        }
    }

    // ---- Epilogue: warp covers rows [m0+r0, +32), cols [cw*64, +64) ----
    #pragma unroll
    for (int mt = 0; mt < 2; mt++) {
        int mlo = m0 + r0 + mt * 16 + grp;
        int mhi = mlo + 8;
        #pragma unroll
        for (int t8 = 0; t8 < 8; t8++) {
            int n = cw * 64 + 8 * t8 + 2 * tig;
            if (mlo < M) {
                __nv_bfloat162 p = __float22bfloat162_rn(make_float2(c[mt][t8][0], c[mt][t8][1]));
                *(__nv_bfloat162*)(C + (size_t)mlo * DIM + n) = p;
            }
            if (mhi < M) {
                __nv_bfloat162 p = __float22bfloat162_rn(make_float2(c[mt][t8][2], c[mt][t8][3]));
                *(__nv_bfloat162*)(C + (size_t)mhi * DIM + n) = p;
            }
        }
    }
}

// ------------------------------- launch ------------------------------------

extern "C" void kernel_launch(void* const* d_in, const int* in_sizes, int n_in,
                              void* d_out, int out_size) {
    const float* x   = (const float*)d_in[0];
    const int*   ei  = (const int*)d_in[1];
    const int*   nidx = ei;
    const int*   hidx = ei + N_INC;
    const float* w1  = (const float*)d_in[2];
    const float* b1  = (const float*)d_in[3];
    const float* w2  = (const float*)d_in[4];
    const float* b2  = (const float*)d_in[5];
    float* out = (float*)d_out;

    __nv_bfloat16 *h, *e, *o;
    float *dinv, *binv, *acc;
    int *cnt_n, *cnt_h, *ell_n, *ell_h;
    uint2 *w1p, *w2p;
    cudaGetSymbolAddress((void**)&h,     g_h);
    cudaGetSymbolAddress((void**)&e,     g_e);
    cudaGetSymbolAddress((void**)&o,     g_o);
    cudaGetSymbolAddress((void**)&dinv,  g_dinv);
    cudaGetSymbolAddress((void**)&binv,  g_binv);
    cudaGetSymbolAddress((void**)&acc,   g_acc);
    cudaGetSymbolAddress((void**)&cnt_n, g_cnt_n);
    cudaGetSymbolAddress((void**)&cnt_h, g_cnt_h);
    cudaGetSymbolAddress((void**)&ell_n, g_ell_n);
    cudaGetSymbolAddress((void**)&ell_h, g_ell_h);
    cudaGetSymbolAddress((void**)&w1p,   g_w1p);
    cudaGetSymbolAddress((void**)&w2p,   g_w2p);

    const int gemm_smem = 64 * BP_STRIDE * 8 + 128 * AS_STRIDE * 4;  // 102400 B
    cudaFuncSetAttribute((const void*)gemm_tc_kernel<false, false>,
                         cudaFuncAttributeMaxDynamicSharedMemorySize, gemm_smem);
    cudaFuncSetAttribute((const void*)gemm_tc_kernel<true, true>,
                         cudaFuncAttributeMaxDynamicSharedMemorySize, gemm_smem);

    const int TB = 256;
    const int zb_nodes = (N_NODES + TB - 1) / TB;
    const int db_inc   = (N_INC + TB - 1) / TB;
    const int gemm_grid = (N_NODES + 127) / 128;
    const int gather_grid = (int)(((long long)N_NODES * 16 + TB - 1) / TB);

    init_kernel<<<zb_nodes, TB>>>(cnt_n, cnt_h, acc, N_NODES);
    pack_w_kernel<<<32, 256>>>(w1, w2, w1p, w2p);
    fill_ell_kernel<<<db_inc, TB>>>(nidx, hidx, cnt_n, cnt_h, ell_n, ell_h, N_INC);
    invert_from_counts<<<zb_nodes, TB>>>(cnt_n, cnt_h, dinv, binv, N_NODES);

    // ---- Layer 1 ----
    gemm_tc_kernel<false, false><<<gemm_grid, TB, gemm_smem>>>(x, w1p, nullptr, nullptr, h, N_NODES);
    gather_kernel<true><<<gather_grid, TB>>>(h, cnt_h, ell_h, binv, e, N_NODES);     // e = Binv H^T h
    gather_kernel<false><<<gather_grid, TB>>>(e, cnt_n, ell_n, nullptr, o, N_NODES); // o = H e

    // ---- Layer 2 (layer-1 dinv/bias/relu fused into GEMM A-staging) ----
    gemm_tc_kernel<true, true><<<gemm_grid, TB, gemm_smem>>>(o, w2p, dinv, b1, h, N_NODES);
    gather_kernel<true><<<gather_grid, TB>>>(h, cnt_h, ell_h, binv, e, N_NODES);     // e2 = Binv H^T h

    // ---- Final: fused node-gather + relu(.*dinv + b2) + column mean ----
    gather_mean_kernel<<<gather_grid, TB>>>(e, cnt_n, ell_n, dinv, b2, acc, N_NODES);
    finalize_kernel<<<1, DIM>>>(acc, out);
}